// round 8
// baseline (speedup 1.0000x reference)
#include <cuda_runtime.h>
#include <cstdint>

#define T_LEN 1024
#define S_LEN 1024
#define BSZ 4
#define EMB 1024
#define NH 16
#define HD 64
#define BH (BSZ*NH)   // 64

// ---------------- scratch (device globals; no allocations allowed) ----------
__device__ float g_q[BH * T_LEN * HD];              // [z=(b,h), t, d] scaled q
__device__ float g_k[BH * S_LEN * HD];              // [z, s, d]
__device__ float g_vt[BH * HD * S_LEN];             // [z, d, s]  (V transposed)
__device__ float g_ctx2[T_LEN * BSZ * EMB];         // [t, b, e]

// ============================================================================
__device__ __forceinline__ uint32_t f2tf32(float f) {
    uint32_t u;
    asm("cvt.rna.tf32.f32 %0, %1;" : "=r"(u) : "f"(f));
    return u;
}
__device__ __forceinline__ void mma16n8k8(float* c, const uint32_t* a, const uint32_t* b) {
    asm volatile(
        "mma.sync.aligned.m16n8k8.row.col.f32.tf32.tf32.f32 "
        "{%0,%1,%2,%3}, {%4,%5,%6,%7}, {%8,%9}, {%0,%1,%2,%3};"
        : "+f"(c[0]), "+f"(c[1]), "+f"(c[2]), "+f"(c[3])
        : "r"(a[0]), "r"(a[1]), "r"(a[2]), "r"(a[3]), "r"(b[0]), "r"(b[1]));
}

// ============================================================================
// Projection GEMM (tf32 mma.sync NT): C[m][n] = sum_k A[m*lda+k] * B[n*ldb+k]
// MODE 0: Q proj   -> g_q (bias, *0.125, [z,t,d] scatter)
// MODE 1: KV proj  -> g_k / g_vt (bias, scatter; V transposed)
// MODE 3: out proj -> Cout (+bias)
// ============================================================================
#define SROW 20

template<int TN, int MODE>
__global__ __launch_bounds__(256)
void gemm_mma(const float* __restrict__ Ain, int lda,
              const float* __restrict__ Bin, int ldb,
              const float* __restrict__ bias,
              float* __restrict__ Cout, int K)
{
    constexpr int FN = TN / 16;
    __shared__ uint32_t As[2][128 * SROW];
    __shared__ uint32_t Bs[2][TN * SROW];

    const int tid = threadIdx.x;
    const int wid = tid >> 5, lane = tid & 31;
    const int wm = wid & 3, wn = wid >> 2;
    const int g = lane >> 2, t4 = lane & 3;
    const int m0 = blockIdx.y * 128;
    const int n0 = blockIdx.x * TN;

    const float* A = (MODE == 3) ? g_ctx2 : Ain;
    const float* B = Bin;
    const int NI = K / 16;

    auto load_stage = [&](int s, int k0) {
        #pragma unroll
        for (int r = 0; r < 2; r++) {
            int f4 = tid + r * 256;
            int row = f4 >> 2, c4 = (f4 & 3) * 4;
            float4 v = *(const float4*)(A + (size_t)(m0 + row) * lda + k0 + c4);
            uint4 u = {f2tf32(v.x), f2tf32(v.y), f2tf32(v.z), f2tf32(v.w)};
            *(uint4*)&As[s][row * SROW + c4] = u;
        }
        #pragma unroll
        for (int r = 0; r < TN / 64; r++) {
            int f4 = tid + r * 256;
            int row = f4 >> 2, c4 = (f4 & 3) * 4;
            float4 v = *(const float4*)(B + (size_t)(n0 + row) * ldb + k0 + c4);
            uint4 u = {f2tf32(v.x), f2tf32(v.y), f2tf32(v.z), f2tf32(v.w)};
            *(uint4*)&Bs[s][row * SROW + c4] = u;
        }
    };

    float c[2][FN][4];
    #pragma unroll
    for (int mi = 0; mi < 2; mi++)
        #pragma unroll
        for (int ni = 0; ni < FN; ni++)
            #pragma unroll
            for (int e = 0; e < 4; e++) c[mi][ni][e] = 0.f;

    load_stage(0, 0);
    __syncthreads();

    for (int i = 0; i < NI; i++) {
        int s = i & 1;
        #pragma unroll
        for (int kk = 0; kk < 2; kk++) {
            uint32_t a[2][4], b[FN][2];
            #pragma unroll
            for (int mi = 0; mi < 2; mi++) {
                int r = wm * 32 + mi * 16 + g;
                int col = kk * 8 + t4;
                a[mi][0] = As[s][r * SROW + col];
                a[mi][1] = As[s][(r + 8) * SROW + col];
                a[mi][2] = As[s][r * SROW + col + 4];
                a[mi][3] = As[s][(r + 8) * SROW + col + 4];
            }
            #pragma unroll
            for (int ni = 0; ni < FN; ni++) {
                int rn = wn * (TN / 2) + ni * 8 + g;
                int col = kk * 8 + t4;
                b[ni][0] = Bs[s][rn * SROW + col];
                b[ni][1] = Bs[s][rn * SROW + col + 4];
            }
            #pragma unroll
            for (int mi = 0; mi < 2; mi++)
                #pragma unroll
                for (int ni = 0; ni < FN; ni++)
                    mma16n8k8(c[mi][ni], a[mi], b[ni]);
        }
        if (i + 1 < NI) {
            load_stage(s ^ 1, (i + 1) * 16);
            __syncthreads();
        }
    }

    #pragma unroll
    for (int mi = 0; mi < 2; mi++) {
        #pragma unroll
        for (int ni = 0; ni < FN; ni++) {
            #pragma unroll
            for (int e = 0; e < 4; e++) {
                int row = m0 + wm * 32 + mi * 16 + g + ((e >= 2) ? 8 : 0);
                int col = n0 + wn * (TN / 2) + ni * 8 + t4 * 2 + (e & 1);
                float v = c[mi][ni][e];
                if (MODE == 0) {
                    int t = row >> 2, b = row & 3;
                    int h = col >> 6, d = col & 63;
                    g_q[(size_t)(((b << 4) + h) * T_LEN + t) * HD + d] =
                        (v + bias[col]) * 0.125f;
                } else if (MODE == 1) {
                    v += bias[col];
                    int ff = col & 1023;
                    int h = ff >> 6, d = ff & 63;
                    int t = row >> 2, b = row & 3;
                    int zz = (b << 4) + h;
                    if (col < 1024)
                        g_k[(size_t)(zz * S_LEN + t) * HD + d] = v;
                    else
                        g_vt[(size_t)(zz * HD + d) * S_LEN + t] = v;
                } else {
                    Cout[(size_t)row * EMB + col] = v + bias[col];
                }
            }
        }
    }
}

// ============================================================================
// Fused attention, 512 threads (16 warps), per (b, 32-row t-tile), h-loop.
// avg: 64 regs/thread. mask: 2 bitmask regs/thread. K/V double buffered.
// smem: sc[32][1028] | qb[32*68, also ctx staging stride 68] | kv[2][8704]
// ============================================================================
#define SC_STR 1028
#define SC_WORDS (32 * SC_STR)                       // 32896
#define QB_WORDS (32 * 68)                           // 2176
#define KVB_WORDS (128 * 68)                         // 8704 (>= 64*132=8448)
#define ATTN_WORDS (SC_WORDS + QB_WORDS + 2 * KVB_WORDS)
#define ATTN_SMEM_BYTES (ATTN_WORDS * 4)             // 209920

__global__ __launch_bounds__(512, 1)
void attn_fused(const float* __restrict__ mask, float* __restrict__ avg_out)
{
    extern __shared__ uint32_t sh[];
    uint32_t* sc = sh;                      // scores / probs tile
    uint32_t* qb = sh + SC_WORDS;           // Q tile (tf32) / ctx staging
    uint32_t* kv0 = qb + QB_WORDS;          // K/V chunk buf 0
    uint32_t* kv1 = kv0 + KVB_WORDS;        // K/V chunk buf 1

    const int tid = threadIdx.x;
    const int w = tid >> 5, lane = tid & 31;
    const int g = lane >> 2, t4 = lane & 3;
    const int t0 = blockIdx.x * 32;
    const int b  = blockIdx.y;

    // softmax/avg ownership: row sr = tid>>4, cols c0+16j (j<64)
    const int sr = tid >> 4;
    const int c0 = tid & 15;

    // pack this thread's 64 mask values into 2 bitmask registers (mask is 0/1)
    uint32_t mkb0 = 0, mkb1 = 0;
    {
        const float* mrow = mask + ((size_t)(b * T_LEN + t0 + sr)) * S_LEN;
        #pragma unroll
        for (int j = 0; j < 32; j++)
            if (mrow[c0 + 16 * j] != 0.f) mkb0 |= (1u << j);
        #pragma unroll
        for (int j = 0; j < 32; j++)
            if (mrow[c0 + 16 * (j + 32)] != 0.f) mkb1 |= (1u << j);
    }

    float avg[64];
    #pragma unroll
    for (int j = 0; j < 64; j++) avg[j] = 0.f;

    for (int h = 0; h < NH; h++) {
        const int z = (b << 4) + h;
        const float* Qz = g_q + (size_t)z * (T_LEN * HD);
        const float* Kz = g_k + (size_t)z * (S_LEN * HD);
        const float* Vz = g_vt + (size_t)z * (HD * S_LEN);

        __syncthreads();   // qb/sc/kv free from prior head

        // ---- load Q tile 32x64 -> qb (tf32), stride 68; + K chunk 0 -> kv0
        {
            int f4 = tid;                   // 0..511 (= 32*64/4)
            int row = f4 >> 4, c4 = (f4 & 15) * 4;
            float4 v = *(const float4*)(Qz + (size_t)(t0 + row) * HD + c4);
            uint4 u = {f2tf32(v.x), f2tf32(v.y), f2tf32(v.z), f2tf32(v.w)};
            *(uint4*)&qb[row * 68 + c4] = u;
        }
        #pragma unroll
        for (int r = 0; r < 4; r++) {
            int f4 = tid + r * 512;         // 0..2047 (= 128*64/4)
            int row = f4 >> 4, c4 = (f4 & 15) * 4;
            float4 v = *(const float4*)(Kz + (size_t)row * HD + c4);
            uint4 u = {f2tf32(v.x), f2tf32(v.y), f2tf32(v.z), f2tf32(v.w)};
            *(uint4*)&kv0[row * 68 + c4] = u;
        }
        __syncthreads();

        // ---- scores: 8 chunks of 128 s-cols; warp w covers n-cols [w*8, w*8+8)
        for (int ch = 0; ch < 8; ch++) {
            uint32_t* kb = (ch & 1) ? kv1 : kv0;
            if (ch < 7) {
                uint32_t* kn = (ch & 1) ? kv0 : kv1;
                int s0n = (ch + 1) * 128;
                #pragma unroll
                for (int r = 0; r < 4; r++) {
                    int f4 = tid + r * 512;
                    int row = f4 >> 4, c4 = (f4 & 15) * 4;
                    float4 v = *(const float4*)(Kz + (size_t)(s0n + row) * HD + c4);
                    uint4 u = {f2tf32(v.x), f2tf32(v.y), f2tf32(v.z), f2tf32(v.w)};
                    *(uint4*)&kn[row * 68 + c4] = u;
                }
            }

            float c[2][4];
            #pragma unroll
            for (int mi = 0; mi < 2; mi++)
                #pragma unroll
                for (int e = 0; e < 4; e++) c[mi][e] = 0.f;

            #pragma unroll
            for (int kk = 0; kk < 8; kk++) {
                int col = kk * 8 + t4;
                uint32_t a[2][4], bb[2];
                #pragma unroll
                for (int mi = 0; mi < 2; mi++) {
                    int r = mi * 16 + g;
                    a[mi][0] = qb[r * 68 + col];
                    a[mi][1] = qb[(r + 8) * 68 + col];
                    a[mi][2] = qb[r * 68 + col + 4];
                    a[mi][3] = qb[(r + 8) * 68 + col + 4];
                }
                int rn = w * 8 + g;
                bb[0] = kb[rn * 68 + col];
                bb[1] = kb[rn * 68 + col + 4];
                #pragma unroll
                for (int mi = 0; mi < 2; mi++)
                    mma16n8k8(c[mi], a[mi], bb);
            }
            // scores -> sc (f32 bits)
            int s0 = ch * 128;
            #pragma unroll
            for (int mi = 0; mi < 2; mi++)
                #pragma unroll
                for (int e = 0; e < 4; e++) {
                    int row = mi * 16 + g + ((e >= 2) ? 8 : 0);
                    int col = s0 + w * 8 + t4 * 2 + (e & 1);
                    sc[row * SC_STR + col] = __float_as_uint(c[mi][e]);
                }
            __syncthreads();
        }

        // ---- softmax + mask(bits) + avg (row sr, cols c0+16j)
        {
            uint32_t* rowp = sc + sr * SC_STR;
            float mx = -1e30f;
            #pragma unroll
            for (int j = 0; j < 64; j++)
                mx = fmaxf(mx, __uint_as_float(rowp[c0 + 16 * j]));
            #pragma unroll
            for (int o = 8; o >= 1; o >>= 1)
                mx = fmaxf(mx, __shfl_xor_sync(0xffffffffu, mx, o));

            float sum = 0.f;
            #pragma unroll
            for (int j = 0; j < 64; j++) {
                float x = __expf(__uint_as_float(rowp[c0 + 16 * j]) - mx);
                rowp[c0 + 16 * j] = __float_as_uint(x);
                sum += x;
            }
            #pragma unroll
            for (int o = 8; o >= 1; o >>= 1)
                sum += __shfl_xor_sync(0xffffffffu, sum, o);
            float inv = 1.f / sum;

            #pragma unroll
            for (int j = 0; j < 64; j++) {
                int col = c0 + 16 * j;
                uint32_t bit = (j < 32) ? (mkb0 >> j) : (mkb1 >> (j - 32));
                float p = (bit & 1u) ? (__uint_as_float(rowp[col]) * inv) : 0.f;
                avg[j] += p;
                rowp[col] = f2tf32(p);
            }
        }

        // ---- PV: ctx[32][64]; warp w: mi=w&1, d-cols [(w>>1)*8, +8)
        float cc[4];
        #pragma unroll
        for (int e = 0; e < 4; e++) cc[e] = 0.f;
        const int mi = w & 1;
        const int n0 = (w >> 1) * 8;

        // V chunk 0 -> kv0 (64 d-rows x 128 s, stride 132)
        #pragma unroll
        for (int r = 0; r < 4; r++) {
            int f4 = tid + r * 512;         // 0..2047
            int row = f4 >> 5, c4 = (f4 & 31) * 4;
            float4 v = *(const float4*)(Vz + (size_t)row * S_LEN + c4);
            uint4 u = {f2tf32(v.x), f2tf32(v.y), f2tf32(v.z), f2tf32(v.w)};
            *(uint4*)&kv0[row * 132 + c4] = u;
        }
        __syncthreads();

        for (int ch = 0; ch < 8; ch++) {
            uint32_t* vb = (ch & 1) ? kv1 : kv0;
            if (ch < 7) {
                uint32_t* vn = (ch & 1) ? kv0 : kv1;
                int s0n = (ch + 1) * 128;
                #pragma unroll
                for (int r = 0; r < 4; r++) {
                    int f4 = tid + r * 512;
                    int row = f4 >> 5, c4 = (f4 & 31) * 4;
                    float4 v = *(const float4*)(Vz + (size_t)row * S_LEN + s0n + c4);
                    uint4 u = {f2tf32(v.x), f2tf32(v.y), f2tf32(v.z), f2tf32(v.w)};
                    *(uint4*)&vn[row * 132 + c4] = u;
                }
            }

            int s0 = ch * 128;
            #pragma unroll
            for (int kk = 0; kk < 16; kk++) {
                int col = kk * 8 + t4;
                uint32_t a[4], bb[2];
                int r = mi * 16 + g;
                a[0] = sc[r * SC_STR + s0 + col];
                a[1] = sc[(r + 8) * SC_STR + s0 + col];
                a[2] = sc[r * SC_STR + s0 + col + 4];
                a[3] = sc[(r + 8) * SC_STR + s0 + col + 4];
                bb[0] = vb[(n0 + g) * 132 + col];
                bb[1] = vb[(n0 + g) * 132 + col + 4];
                mma16n8k8(cc, a, bb);
            }
            __syncthreads();
        }

        // ---- stage ctx in qb (stride 68, 16B-aligned rows), coalesced store
        #pragma unroll
        for (int e = 0; e < 4; e++) {
            int row = mi * 16 + g + ((e >= 2) ? 8 : 0);
            int col = n0 + t4 * 2 + (e & 1);
            qb[row * 68 + col] = __float_as_uint(cc[e]);
        }
        __syncthreads();
        {
            int row = tid >> 4, c4 = (tid & 15) * 4;   // 512*4 = 2048 = 32x64
            uint4 u = *(uint4*)&qb[row * 68 + c4];
            *(uint4*)&g_ctx2[(size_t)((t0 + row) * BSZ + b) * EMB + h * HD + c4] = u;
        }
    }

    // ---- write avg (sum over heads / 16); already masked
    {
        float* arow = avg_out + ((size_t)(b * T_LEN + t0 + sr)) * S_LEN;
        #pragma unroll
        for (int j = 0; j < 64; j++)
            arow[c0 + 16 * j] = avg[j] * (1.0f / NH);
    }
}

// ---------------------------------------------------------------------------
extern "C" void kernel_launch(void* const* d_in, const int* in_sizes, int n_in,
                              void* d_out, int out_size)
{
    const float* query = (const float*)d_in[0];
    const float* key   = (const float*)d_in[1];
    const float* mask  = (const float*)d_in[2];
    const float* w_in  = (const float*)d_in[3];
    const float* b_in  = (const float*)d_in[4];
    const float* w_out = (const float*)d_in[5];
    const float* b_out = (const float*)d_in[6];
    float* out = (float*)d_out;                         // [t][b][e]
    float* avg = out + (size_t)T_LEN * BSZ * EMB;       // [b][t][s]

    cudaFuncSetAttribute(attn_fused, cudaFuncAttributeMaxDynamicSharedMemorySize,
                         ATTN_SMEM_BYTES);

    dim3 blk(256);
    // 1) Q projection
    gemm_mma<128, 0><<<dim3(8, 32, 1), blk>>>(query, EMB, w_in, EMB, b_in, nullptr, EMB);
    // 2) KV projection
    gemm_mma<128, 1><<<dim3(16, 32, 1), blk>>>(key, EMB, w_in + EMB * EMB, EMB,
                                               b_in + EMB, nullptr, EMB);
    // 3) fused attention -> g_ctx2, avg
    attn_fused<<<dim3(32, 4), 512, ATTN_SMEM_BYTES>>>(mask, avg);
    // 4) output projection -> d_out
    gemm_mma<128, 3><<<dim3(8, 32, 1), blk>>>(nullptr, EMB, w_out, EMB, b_out, out, EMB);
}

// round 9
// speedup vs baseline: 1.0912x; 1.0912x over previous
#include <cuda_runtime.h>
#include <cstdint>

#define T_LEN 1024
#define S_LEN 1024
#define BSZ 4
#define EMB 1024
#define NH 16
#define HD 64

// ---------------- scratch (device globals) ----------------------------------
__device__ float g_q[4096 * 1024];                   // [m=t*4+b][f=h*64+d], scaled
__device__ float g_kv[4096 * 2048];                  // [m=s*4+b][f]; f<1024 K, else V
__device__ float g_sc[(size_t)64 * 1024 * 1024];     // probs [z][t][s] (masked, normalized)
__device__ float g_ctx2[4096 * 1024];                // [m=t*4+b][e]
__device__ float g_avgp[2 * 4 * 1024 * 1024];        // partial avg [hg][b][t][s]

// ============================================================================
__device__ __forceinline__ uint32_t f2tf32(float f) {
    uint32_t u;
    asm("cvt.rna.tf32.f32 %0, %1;" : "=r"(u) : "f"(f));
    return u;
}
__device__ __forceinline__ void mma16n8k8(float* c, const uint32_t* a, const uint32_t* b) {
    asm volatile(
        "mma.sync.aligned.m16n8k8.row.col.f32.tf32.tf32.f32 "
        "{%0,%1,%2,%3}, {%4,%5,%6,%7}, {%8,%9}, {%0,%1,%2,%3};"
        : "+f"(c[0]), "+f"(c[1]), "+f"(c[2]), "+f"(c[3])
        : "r"(a[0]), "r"(a[1]), "r"(a[2]), "r"(a[3]), "r"(b[0]), "r"(b[1]));
}

// ============================================================================
// Projection GEMM (tf32 mma.sync NT): C[m][n] = sum_k A[m*1024+k]*B[n*1024+k]
// All outputs row-major (coalesced):
//  MODE 0: g_q[m][col]  = (v+bias)*0.125
//  MODE 1: g_kv[m][col] =  v+bias          (TN=128, grid.x=16 -> 2048 cols)
//  MODE 3: Cout[m][col] =  v+bias
// ============================================================================
#define SROW 20

template<int MODE>
__global__ __launch_bounds__(256)
void gemm_mma(const float* __restrict__ Ain,
              const float* __restrict__ Bin,
              const float* __restrict__ bias,
              float* __restrict__ Cout)
{
    __shared__ uint32_t As[2][128 * SROW];
    __shared__ uint32_t Bs[2][128 * SROW];

    const int tid = threadIdx.x;
    const int wid = tid >> 5, lane = tid & 31;
    const int wm = wid & 3, wn = wid >> 2;
    const int g = lane >> 2, t4 = lane & 3;
    const int m0 = blockIdx.y * 128;
    const int n0 = blockIdx.x * 128;

    const float* A = (MODE == 3) ? g_ctx2 : Ain;
    const float* B = Bin;

    auto load_stage = [&](int s, int k0) {
        #pragma unroll
        for (int r = 0; r < 2; r++) {
            int f4 = tid + r * 256;
            int row = f4 >> 2, c4 = (f4 & 3) * 4;
            float4 v = *(const float4*)(A + (size_t)(m0 + row) * 1024 + k0 + c4);
            uint4 u = {f2tf32(v.x), f2tf32(v.y), f2tf32(v.z), f2tf32(v.w)};
            *(uint4*)&As[s][row * SROW + c4] = u;
        }
        #pragma unroll
        for (int r = 0; r < 2; r++) {
            int f4 = tid + r * 256;
            int row = f4 >> 2, c4 = (f4 & 3) * 4;
            float4 v = *(const float4*)(B + (size_t)(n0 + row) * 1024 + k0 + c4);
            uint4 u = {f2tf32(v.x), f2tf32(v.y), f2tf32(v.z), f2tf32(v.w)};
            *(uint4*)&Bs[s][row * SROW + c4] = u;
        }
    };

    float c[2][8][4];
    #pragma unroll
    for (int mi = 0; mi < 2; mi++)
        #pragma unroll
        for (int ni = 0; ni < 8; ni++)
            #pragma unroll
            for (int e = 0; e < 4; e++) c[mi][ni][e] = 0.f;

    load_stage(0, 0);
    __syncthreads();

    for (int i = 0; i < 64; i++) {
        int s = i & 1;
        #pragma unroll
        for (int kk = 0; kk < 2; kk++) {
            uint32_t a[2][4], b[8][2];
            #pragma unroll
            for (int mi = 0; mi < 2; mi++) {
                int r = wm * 32 + mi * 16 + g;
                int col = kk * 8 + t4;
                a[mi][0] = As[s][r * SROW + col];
                a[mi][1] = As[s][(r + 8) * SROW + col];
                a[mi][2] = As[s][r * SROW + col + 4];
                a[mi][3] = As[s][(r + 8) * SROW + col + 4];
            }
            #pragma unroll
            for (int ni = 0; ni < 8; ni++) {
                int rn = wn * 64 + ni * 8 + g;
                int col = kk * 8 + t4;
                b[ni][0] = Bs[s][rn * SROW + col];
                b[ni][1] = Bs[s][rn * SROW + col + 4];
            }
            #pragma unroll
            for (int mi = 0; mi < 2; mi++)
                #pragma unroll
                for (int ni = 0; ni < 8; ni++)
                    mma16n8k8(c[mi][ni], a[mi], b[ni]);
        }
        if (i + 1 < 64) {
            load_stage(s ^ 1, (i + 1) * 16);
            __syncthreads();
        }
    }

    const size_t ldc = (MODE == 1) ? 2048 : 1024;
    #pragma unroll
    for (int mi = 0; mi < 2; mi++) {
        #pragma unroll
        for (int ni = 0; ni < 8; ni++) {
            #pragma unroll
            for (int e = 0; e < 4; e++) {
                int row = m0 + wm * 32 + mi * 16 + g + ((e >= 2) ? 8 : 0);
                int col = n0 + wn * 64 + ni * 8 + t4 * 2 + (e & 1);
                float v = c[mi][ni][e] + bias[col];
                if (MODE == 0)      g_q[(size_t)row * 1024 + col] = v * 0.125f;
                else if (MODE == 1) g_kv[(size_t)row * 2048 + col] = v;
                else                Cout[(size_t)row * 1024 + col] = v;
            }
        }
    }
}

// ============================================================================
// Scores + softmax + mask -> probs (f32). Per CTA: (z=(b,h), 32 t-rows), full S.
// 256 threads, 8 warps; warp tile 32x16 per 128-col chunk; K double-buffered.
// Row max via fragment shuffles; exp stored in smem; linear masked write.
// smem: sc[32*1028] | qb[32*68 -> stats alias] | kv[2][128*68]
// ============================================================================
#define SC_STR 1028
#define SC_WORDS (32 * SC_STR)
#define QB_WORDS (32 * 68)
#define KVB_WORDS (128 * 68)
#define SS_SMEM_BYTES ((SC_WORDS + QB_WORDS + 2 * KVB_WORDS) * 4)  // 209920

__global__ __launch_bounds__(256, 1)
void scores_softmax(const float* __restrict__ mask)
{
    extern __shared__ uint32_t sh[];
    uint32_t* sc  = sh;
    uint32_t* qb  = sh + SC_WORDS;     // Q tile; stats after MMAs
    uint32_t* kv0 = qb + QB_WORDS;
    uint32_t* kv1 = kv0 + KVB_WORDS;

    const int tid = threadIdx.x;
    const int w = tid >> 5, lane = tid & 31;
    const int g = lane >> 2, t4 = lane & 3;
    const int t0 = blockIdx.x * 32;
    const int z  = blockIdx.y;
    const int b  = z >> 4;
    const int fq = (z & 15) * HD;

    // Q tile 32x64 -> qb (tf32, stride 68)
    #pragma unroll
    for (int r = 0; r < 2; r++) {
        int idx = tid + r * 256;
        int row = idx >> 4, c4 = (idx & 15) * 4;
        float4 v = *(const float4*)(g_q + (size_t)((t0 + row) * 4 + b) * 1024 + fq + c4);
        uint4 u = {f2tf32(v.x), f2tf32(v.y), f2tf32(v.z), f2tf32(v.w)};
        *(uint4*)&qb[row * 68 + c4] = u;
    }

    auto loadK = [&](uint32_t* dst, int s0) {
        #pragma unroll
        for (int r = 0; r < 8; r++) {
            int idx = tid + r * 256;          // 2048 f4
            int srow = idx >> 4, c4 = (idx & 15) * 4;
            float4 v = *(const float4*)(g_kv + (size_t)((s0 + srow) * 4 + b) * 2048 + fq + c4);
            uint4 u = {f2tf32(v.x), f2tf32(v.y), f2tf32(v.z), f2tf32(v.w)};
            *(uint4*)&dst[srow * 68 + c4] = u;
        }
    };
    loadK(kv0, 0);
    __syncthreads();

    float mxp[4] = {-1e30f, -1e30f, -1e30f, -1e30f};

    for (int ch = 0; ch < 8; ch++) {
        uint32_t* kb = (ch & 1) ? kv1 : kv0;
        if (ch < 7) loadK((ch & 1) ? kv0 : kv1, (ch + 1) * 128);

        float c[2][2][4];
        #pragma unroll
        for (int mi = 0; mi < 2; mi++)
            #pragma unroll
            for (int ni = 0; ni < 2; ni++)
                #pragma unroll
                for (int e = 0; e < 4; e++) c[mi][ni][e] = 0.f;

        #pragma unroll
        for (int kk = 0; kk < 8; kk++) {
            int col = kk * 8 + t4;
            uint32_t a[2][4], bb[2][2];
            #pragma unroll
            for (int mi = 0; mi < 2; mi++) {
                int r = mi * 16 + g;
                a[mi][0] = qb[r * 68 + col];
                a[mi][1] = qb[(r + 8) * 68 + col];
                a[mi][2] = qb[r * 68 + col + 4];
                a[mi][3] = qb[(r + 8) * 68 + col + 4];
            }
            #pragma unroll
            for (int ni = 0; ni < 2; ni++) {
                int rn = w * 16 + ni * 8 + g;
                bb[ni][0] = kb[rn * 68 + col];
                bb[ni][1] = kb[rn * 68 + col + 4];
            }
            #pragma unroll
            for (int mi = 0; mi < 2; mi++)
                #pragma unroll
                for (int ni = 0; ni < 2; ni++)
                    mma16n8k8(c[mi][ni], a[mi], bb[ni]);
        }
        #pragma unroll
        for (int mi = 0; mi < 2; mi++)
            #pragma unroll
            for (int ni = 0; ni < 2; ni++)
                #pragma unroll
                for (int e = 0; e < 4; e++) {
                    int row = mi * 16 + g + ((e >= 2) ? 8 : 0);
                    int col = ch * 128 + w * 16 + ni * 8 + t4 * 2 + (e & 1);
                    sc[row * SC_STR + col] = __float_as_uint(c[mi][ni][e]);
                    int p = mi * 2 + (e >> 1);
                    mxp[p] = fmaxf(mxp[p], c[mi][ni][e]);
                }
        __syncthreads();
    }

    // cross-t4 max, then per-warp partial -> stats (qb alias; all MMAs done)
    #pragma unroll
    for (int o = 1; o <= 2; o <<= 1) {
        #pragma unroll
        for (int p = 0; p < 4; p++)
            mxp[p] = fmaxf(mxp[p], __shfl_xor_sync(0xffffffffu, mxp[p], o));
    }
    if (t4 == 0) {
        qb[(g)      * 8 + w] = __float_as_uint(mxp[0]);
        qb[(g + 8)  * 8 + w] = __float_as_uint(mxp[1]);
        qb[(g + 16) * 8 + w] = __float_as_uint(mxp[2]);
        qb[(g + 24) * 8 + w] = __float_as_uint(mxp[3]);
    }
    __syncthreads();

    // row max; exp+sum pass (thread: row tid>>3, cols (tid&7)*4 + 32j)
    const int srow = tid >> 3, l8 = tid & 7;
    float mx = -1e30f;
    #pragma unroll
    for (int i = 0; i < 8; i++)
        mx = fmaxf(mx, __uint_as_float(qb[srow * 8 + i]));

    float sum = 0.f;
    #pragma unroll
    for (int j = 0; j < 32; j++) {
        uint32_t* p = &sc[srow * SC_STR + l8 * 4 + 32 * j];
        uint4 u = *(uint4*)p;
        float x0 = __expf(__uint_as_float(u.x) - mx);
        float x1 = __expf(__uint_as_float(u.y) - mx);
        float x2 = __expf(__uint_as_float(u.z) - mx);
        float x3 = __expf(__uint_as_float(u.w) - mx);
        sum += (x0 + x1) + (x2 + x3);
        u.x = __float_as_uint(x0); u.y = __float_as_uint(x1);
        u.z = __float_as_uint(x2); u.w = __float_as_uint(x3);
        *(uint4*)p = u;
    }
    #pragma unroll
    for (int o = 1; o <= 4; o <<= 1)
        sum += __shfl_xor_sync(0xffffffffu, sum, o);
    if (l8 == 0) qb[512 + srow] = __float_as_uint(1.f / sum);
    __syncthreads();

    // linear masked normalize + coalesced probs write
    float* out = g_sc + (size_t)z * (1024 * 1024) + (size_t)t0 * 1024;
    #pragma unroll
    for (int r = 0; r < 32; r++) {
        int idx = tid + r * 256;             // 8192 f4
        int rr = idx >> 8, c4 = (idx & 255) * 4;
        uint4 u = *(uint4*)&sc[rr * SC_STR + c4];
        float inv = __uint_as_float(qb[512 + rr]);
        float4 mk = *(const float4*)(mask + ((size_t)(b * 1024 + t0 + rr)) * 1024 + c4);
        float4 o4;
        o4.x = __uint_as_float(u.x) * inv * mk.x;
        o4.y = __uint_as_float(u.y) * inv * mk.y;
        o4.z = __uint_as_float(u.z) * inv * mk.z;
        o4.w = __uint_as_float(u.w) * inv * mk.w;
        *(float4*)(out + (size_t)rr * 1024 + c4) = o4;
    }
}

// ============================================================================
// PV + avg partial. Per CTA: (b, 32 t-rows, head-group of 8). 512 threads.
// avg in 64 regs accumulated during coalesced probs staging. V transposed in
// smem. ctx written directly to [t,b,e].
// smem: pb[32*132] | vt[2][64*133] | cstage[32*68]  = 93696 B
// ============================================================================
#define PB_STR 132
#define VT_STR 133
#define PB_WORDS (32 * PB_STR)
#define VT_WORDS (64 * VT_STR)
#define CST_WORDS (32 * 68)
#define PV_SMEM_BYTES ((PB_WORDS + 2 * VT_WORDS + CST_WORDS) * 4)

__global__ __launch_bounds__(512, 1)
void pv_avg()
{
    extern __shared__ uint32_t sh[];
    uint32_t* pb  = sh;
    uint32_t* vt0 = sh + PB_WORDS;
    uint32_t* vt1 = vt0 + VT_WORDS;
    uint32_t* cst = vt1 + VT_WORDS;

    const int tid = threadIdx.x;
    const int w = tid >> 5, lane = tid & 31;
    const int g = lane >> 2, t4 = lane & 3;
    const int t0 = blockIdx.x * 32;
    const int b  = blockIdx.y;
    const int hg = blockIdx.z;

    const int sr  = tid >> 4;      // probs row ownership
    const int l16 = tid & 15;
    const int miw = w & 1;         // MMA warp tile 16x8
    const int n0  = (w >> 1) * 8;

    float avg[64];
    #pragma unroll
    for (int j = 0; j < 64; j++) avg[j] = 0.f;

    for (int hh = 0; hh < 8; hh++) {
        const int h = hg * 8 + hh;
        const int z = b * 16 + h;
        const float* P = g_sc + (size_t)z * (1024 * 1024) + (size_t)t0 * 1024;

        float cc[4] = {0.f, 0.f, 0.f, 0.f};

        for (int ch = 0; ch < 8; ch++) {
            __syncthreads();   // prev chunk MMA done: pb/vt buffer free
            uint32_t* vtb = (ch & 1) ? vt1 : vt0;

            // stage P chunk (32x128) + avg accumulate; thread cols: l16*4 + 64i
            {
                const float* pr = P + (size_t)sr * 1024 + ch * 128 + l16 * 4;
                float4 p0 = *(const float4*)(pr);
                float4 p1 = *(const float4*)(pr + 64);
                avg[ch * 8 + 0] += p0.x; avg[ch * 8 + 1] += p0.y;
                avg[ch * 8 + 2] += p0.z; avg[ch * 8 + 3] += p0.w;
                avg[ch * 8 + 4] += p1.x; avg[ch * 8 + 5] += p1.y;
                avg[ch * 8 + 6] += p1.z; avg[ch * 8 + 7] += p1.w;
                uint4 u0 = {f2tf32(p0.x), f2tf32(p0.y), f2tf32(p0.z), f2tf32(p0.w)};
                uint4 u1 = {f2tf32(p1.x), f2tf32(p1.y), f2tf32(p1.z), f2tf32(p1.w)};
                *(uint4*)&pb[sr * PB_STR + l16 * 4] = u0;
                *(uint4*)&pb[sr * PB_STR + 64 + l16 * 4] = u1;
            }
            // stage V chunk transposed: vt[d][s]
            #pragma unroll
            for (int r = 0; r < 4; r++) {
                int idx = tid + r * 512;      // 2048 f4
                int s = idx >> 4, d4 = (idx & 15) * 4;
                float4 v = *(const float4*)(g_kv +
                    (size_t)((ch * 128 + s) * 4 + b) * 2048 + 1024 + h * 64 + d4);
                vtb[(d4 + 0) * VT_STR + s] = f2tf32(v.x);
                vtb[(d4 + 1) * VT_STR + s] = f2tf32(v.y);
                vtb[(d4 + 2) * VT_STR + s] = f2tf32(v.z);
                vtb[(d4 + 3) * VT_STR + s] = f2tf32(v.w);
            }
            __syncthreads();

            #pragma unroll
            for (int kk = 0; kk < 16; kk++) {
                int col = kk * 8 + t4;
                uint32_t a[4], bb[2];
                int r = miw * 16 + g;
                a[0] = pb[r * PB_STR + col];
                a[1] = pb[(r + 8) * PB_STR + col];
                a[2] = pb[r * PB_STR + col + 4];
                a[3] = pb[(r + 8) * PB_STR + col + 4];
                bb[0] = vtb[(n0 + g) * VT_STR + col];
                bb[1] = vtb[(n0 + g) * VT_STR + col + 4];
                mma16n8k8(cc, a, bb);
            }
        }

        // stage ctx tile then coalesced store to [t,b,e]
        __syncthreads();
        #pragma unroll
        for (int e = 0; e < 4; e++) {
            int row = miw * 16 + g + ((e >= 2) ? 8 : 0);
            int col = n0 + t4 * 2 + (e & 1);
            cst[row * 68 + col] = __float_as_uint(cc[e]);
        }
        __syncthreads();
        {
            int row = tid >> 4, c4 = (tid & 15) * 4;     // 512 f4 = 32x64
            uint4 u = *(uint4*)&cst[row * 68 + c4];
            *(uint4*)&g_ctx2[(size_t)((t0 + row) * 4 + b) * 1024 + h * 64 + c4] = u;
        }
    }

    // write avg partial [hg][b][t][s]
    float* ap = g_avgp + ((size_t)(hg * 4 + b) * 1024 + (t0 + sr)) * 1024;
    #pragma unroll
    for (int ch = 0; ch < 8; ch++)
        #pragma unroll
        for (int i2 = 0; i2 < 2; i2++) {
            float4 o4 = {avg[ch * 8 + i2 * 4 + 0], avg[ch * 8 + i2 * 4 + 1],
                         avg[ch * 8 + i2 * 4 + 2], avg[ch * 8 + i2 * 4 + 3]};
            *(float4*)(ap + ch * 128 + i2 * 64 + l16 * 4) = o4;
        }
}

// avg = (part0 + part1) / 16
__global__ __launch_bounds__(256)
void avg_reduce(float* __restrict__ avg_out)
{
    size_t i = (size_t)blockIdx.x * 256 + threadIdx.x;   // f4 index, 1M total
    const float4* p0 = (const float4*)g_avgp;
    const float4* p1 = p0 + (size_t)4 * 1024 * 1024 / 4;
    float4 a = p0[i], c = p1[i];
    float4 o = {(a.x + c.x) * 0.0625f, (a.y + c.y) * 0.0625f,
                (a.z + c.z) * 0.0625f, (a.w + c.w) * 0.0625f};
    ((float4*)avg_out)[i] = o;
}

// ---------------------------------------------------------------------------
extern "C" void kernel_launch(void* const* d_in, const int* in_sizes, int n_in,
                              void* d_out, int out_size)
{
    const float* query = (const float*)d_in[0];
    const float* key   = (const float*)d_in[1];
    const float* mask  = (const float*)d_in[2];
    const float* w_in  = (const float*)d_in[3];
    const float* b_in  = (const float*)d_in[4];
    const float* w_out = (const float*)d_in[5];
    const float* b_out = (const float*)d_in[6];
    float* out = (float*)d_out;                         // [t][b][e]
    float* avg = out + (size_t)T_LEN * BSZ * EMB;       // [b][t][s]

    cudaFuncSetAttribute(scores_softmax, cudaFuncAttributeMaxDynamicSharedMemorySize,
                         SS_SMEM_BYTES);
    cudaFuncSetAttribute(pv_avg, cudaFuncAttributeMaxDynamicSharedMemorySize,
                         PV_SMEM_BYTES);

    // 1) Q projection  -> g_q row-major (scaled)
    gemm_mma<0><<<dim3(8, 32), 256>>>(query, w_in, b_in, nullptr);
    // 2) KV projection -> g_kv row-major
    gemm_mma<1><<<dim3(16, 32), 256>>>(key, w_in + EMB * EMB, b_in + EMB, nullptr);
    // 3) scores + softmax + mask -> probs
    scores_softmax<<<dim3(32, 64), 256, SS_SMEM_BYTES>>>(mask);
    // 4) PV + avg partials -> g_ctx2, g_avgp
    pv_avg<<<dim3(32, 4, 2), 512, PV_SMEM_BYTES>>>();
    // 5) avg partials -> avg output
    avg_reduce<<<4096, 256>>>(avg);
    // 6) output projection -> d_out
    gemm_mma<3><<<dim3(8, 32), 256>>>(nullptr, w_out, b_out, out);
}

// round 10
// speedup vs baseline: 1.1596x; 1.0627x over previous
#include <cuda_runtime.h>
#include <cstdint>

#define T_LEN 1024
#define S_LEN 1024
#define BSZ 4
#define EMB 1024
#define NH 16
#define HD 64

// ---------------- scratch (device globals) ----------------------------------
__device__ float g_q[4096 * 1024];                   // [m=t*4+b][f=h*64+d], scaled
__device__ float g_k[4096 * 1024];                   // [m=s*4+b][f=h*64+d]
__device__ float g_vt[64 * 64 * 1024];               // [z=(b,h)][d][s]  (V transposed)
__device__ float g_sc[(size_t)64 * 1024 * 1024];     // masked probs [z][t][s] (256MB)
__device__ float g_ctx2[4096 * 1024];                // [m=t*4+b][e]

// ============================================================================
__device__ __forceinline__ uint32_t f2tf32(float f) {
    uint32_t u;
    asm("cvt.rna.tf32.f32 %0, %1;" : "=r"(u) : "f"(f));
    return u;
}
__device__ __forceinline__ void mma16n8k8(float* c, const uint32_t* a, const uint32_t* b) {
    asm volatile(
        "mma.sync.aligned.m16n8k8.row.col.f32.tf32.tf32.f32 "
        "{%0,%1,%2,%3}, {%4,%5,%6,%7}, {%8,%9}, {%0,%1,%2,%3};"
        : "+f"(c[0]), "+f"(c[1]), "+f"(c[2]), "+f"(c[3])
        : "r"(a[0]), "r"(a[1]), "r"(a[2]), "r"(a[3]), "r"(b[0]), "r"(b[1]));
}

// ============================================================================
// Projection GEMM (tf32 mma.sync NT), tile 128x64, 8 warps (4m x 2n),
// warp tile 32x32. Double-buffered BK=16. ~31KB smem -> 3 CTAs/SM.
//  MODE 0: g_q[m][col]  = (v+bias)*0.125          grid (16,32)
//  MODE 1: col<1024 -> g_k[m][col]=v+bias; else V scatter to g_vt  grid (32,32)
//  MODE 3: Cout[m][col] = v+bias                  grid (16,32)
// ============================================================================
#define SROW 20

template<int MODE>
__global__ __launch_bounds__(256)
void gemm_mma(const float* __restrict__ Ain,
              const float* __restrict__ Bin,
              const float* __restrict__ bias,
              float* __restrict__ Cout)
{
    __shared__ uint32_t As[2][128 * SROW];
    __shared__ uint32_t Bs[2][64 * SROW];

    const int tid = threadIdx.x;
    const int wid = tid >> 5, lane = tid & 31;
    const int wm = wid & 3, wn = wid >> 2;
    const int g = lane >> 2, t4 = lane & 3;
    const int m0 = blockIdx.y * 128;
    const int n0 = blockIdx.x * 64;

    const float* A = (MODE == 3) ? g_ctx2 : Ain;
    const float* B = Bin;

    auto load_stage = [&](int s, int k0) {
        #pragma unroll
        for (int r = 0; r < 2; r++) {
            int f4 = tid + r * 256;
            int row = f4 >> 2, c4 = (f4 & 3) * 4;
            float4 v = *(const float4*)(A + (size_t)(m0 + row) * 1024 + k0 + c4);
            uint4 u = {f2tf32(v.x), f2tf32(v.y), f2tf32(v.z), f2tf32(v.w)};
            *(uint4*)&As[s][row * SROW + c4] = u;
        }
        {
            int row = tid >> 2, c4 = (tid & 3) * 4;
            float4 v = *(const float4*)(B + (size_t)(n0 + row) * 1024 + k0 + c4);
            uint4 u = {f2tf32(v.x), f2tf32(v.y), f2tf32(v.z), f2tf32(v.w)};
            *(uint4*)&Bs[s][row * SROW + c4] = u;
        }
    };

    float c[2][4][4];
    #pragma unroll
    for (int mi = 0; mi < 2; mi++)
        #pragma unroll
        for (int ni = 0; ni < 4; ni++)
            #pragma unroll
            for (int e = 0; e < 4; e++) c[mi][ni][e] = 0.f;

    load_stage(0, 0);
    __syncthreads();

    for (int i = 0; i < 64; i++) {
        int s = i & 1;
        #pragma unroll
        for (int kk = 0; kk < 2; kk++) {
            uint32_t a[2][4], b[4][2];
            int col = kk * 8 + t4;
            #pragma unroll
            for (int mi = 0; mi < 2; mi++) {
                int r = wm * 32 + mi * 16 + g;
                a[mi][0] = As[s][r * SROW + col];
                a[mi][1] = As[s][(r + 8) * SROW + col];
                a[mi][2] = As[s][r * SROW + col + 4];
                a[mi][3] = As[s][(r + 8) * SROW + col + 4];
            }
            #pragma unroll
            for (int ni = 0; ni < 4; ni++) {
                int rn = wn * 32 + ni * 8 + g;
                b[ni][0] = Bs[s][rn * SROW + col];
                b[ni][1] = Bs[s][rn * SROW + col + 4];
            }
            #pragma unroll
            for (int mi = 0; mi < 2; mi++)
                #pragma unroll
                for (int ni = 0; ni < 4; ni++)
                    mma16n8k8(c[mi][ni], a[mi], b[ni]);
        }
        if (i + 1 < 64) {
            load_stage(s ^ 1, (i + 1) * 16);
            __syncthreads();
        }
    }

    #pragma unroll
    for (int mi = 0; mi < 2; mi++) {
        #pragma unroll
        for (int ni = 0; ni < 4; ni++) {
            #pragma unroll
            for (int e = 0; e < 4; e++) {
                int row = m0 + wm * 32 + mi * 16 + g + ((e >= 2) ? 8 : 0);
                int col = n0 + wn * 32 + ni * 8 + t4 * 2 + (e & 1);
                float v = c[mi][ni][e] + bias[col];
                if (MODE == 0) {
                    g_q[(size_t)row * 1024 + col] = v * 0.125f;
                } else if (MODE == 1) {
                    if (col < 1024) {
                        g_k[(size_t)row * 1024 + col] = v;
                    } else {
                        int ff = col - 1024;
                        int h = ff >> 6, d = ff & 63;
                        int s = row >> 2, b = row & 3;
                        g_vt[(size_t)(((b << 4) + h) * 64 + d) * 1024 + s] = v;
                    }
                } else {
                    Cout[(size_t)row * 1024 + col] = v + 0.f;
                }
            }
        }
    }
}

// ============================================================================
// Fused attention per (z, 32-t tile): scores + softmax + mask + probs-write +
// PV. Probs kept in smem (tf32) for PV; masked f32 probs -> g_sc for avg_sum.
// 256 threads, 8 warps. smem 209920 B.
// ============================================================================
#define SC_STR 1028
#define SC_WORDS (32 * SC_STR)
#define QB_WORDS (32 * 68)
#define KVB_WORDS (128 * 68)
#define ATT_SMEM_BYTES ((SC_WORDS + QB_WORDS + 2 * KVB_WORDS) * 4)  // 209920

__global__ __launch_bounds__(256, 1)
void attn_fused(const float* __restrict__ mask)
{
    extern __shared__ uint32_t sh[];
    uint32_t* sc  = sh;
    uint32_t* qb  = sh + SC_WORDS;     // Q tile; stats + ctx staging after MMAs
    uint32_t* kv0 = qb + QB_WORDS;
    uint32_t* kv1 = kv0 + KVB_WORDS;

    const int tid = threadIdx.x;
    const int w = tid >> 5, lane = tid & 31;
    const int g = lane >> 2, t4 = lane & 3;
    const int t0 = blockIdx.x * 32;
    const int z  = blockIdx.y;
    const int b  = z >> 4;
    const int fq = (z & 15) * HD;

    // ---- Q tile 32x64 -> qb (tf32, stride 68)
    #pragma unroll
    for (int r = 0; r < 2; r++) {
        int idx = tid + r * 256;
        int row = idx >> 4, c4 = (idx & 15) * 4;
        float4 v = *(const float4*)(g_q + (size_t)((t0 + row) * 4 + b) * 1024 + fq + c4);
        uint4 u = {f2tf32(v.x), f2tf32(v.y), f2tf32(v.z), f2tf32(v.w)};
        *(uint4*)&qb[row * 68 + c4] = u;
    }

    auto loadK = [&](uint32_t* dst, int s0) {
        #pragma unroll
        for (int r = 0; r < 8; r++) {
            int idx = tid + r * 256;          // 2048 f4
            int srow = idx >> 4, c4 = (idx & 15) * 4;
            float4 v = *(const float4*)(g_k + (size_t)((s0 + srow) * 4 + b) * 1024 + fq + c4);
            uint4 u = {f2tf32(v.x), f2tf32(v.y), f2tf32(v.z), f2tf32(v.w)};
            *(uint4*)&dst[srow * 68 + c4] = u;
        }
    };
    loadK(kv0, 0);
    __syncthreads();

    // ---- scores: 8 chunks of 128 s-cols; warp tile 32x16
    float mxp[4] = {-1e30f, -1e30f, -1e30f, -1e30f};

    for (int ch = 0; ch < 8; ch++) {
        uint32_t* kb = (ch & 1) ? kv1 : kv0;
        if (ch < 7) loadK((ch & 1) ? kv0 : kv1, (ch + 1) * 128);

        float c[2][2][4];
        #pragma unroll
        for (int mi = 0; mi < 2; mi++)
            #pragma unroll
            for (int ni = 0; ni < 2; ni++)
                #pragma unroll
                for (int e = 0; e < 4; e++) c[mi][ni][e] = 0.f;

        #pragma unroll
        for (int kk = 0; kk < 8; kk++) {
            int col = kk * 8 + t4;
            uint32_t a[2][4], bb[2][2];
            #pragma unroll
            for (int mi = 0; mi < 2; mi++) {
                int r = mi * 16 + g;
                a[mi][0] = qb[r * 68 + col];
                a[mi][1] = qb[(r + 8) * 68 + col];
                a[mi][2] = qb[r * 68 + col + 4];
                a[mi][3] = qb[(r + 8) * 68 + col + 4];
            }
            #pragma unroll
            for (int ni = 0; ni < 2; ni++) {
                int rn = w * 16 + ni * 8 + g;
                bb[ni][0] = kb[rn * 68 + col];
                bb[ni][1] = kb[rn * 68 + col + 4];
            }
            #pragma unroll
            for (int mi = 0; mi < 2; mi++)
                #pragma unroll
                for (int ni = 0; ni < 2; ni++)
                    mma16n8k8(c[mi][ni], a[mi], bb[ni]);
        }
        #pragma unroll
        for (int mi = 0; mi < 2; mi++)
            #pragma unroll
            for (int ni = 0; ni < 2; ni++)
                #pragma unroll
                for (int e = 0; e < 4; e++) {
                    int row = mi * 16 + g + ((e >= 2) ? 8 : 0);
                    int col = ch * 128 + w * 16 + ni * 8 + t4 * 2 + (e & 1);
                    sc[row * SC_STR + col] = __float_as_uint(c[mi][ni][e]);
                    int p = mi * 2 + (e >> 1);
                    mxp[p] = fmaxf(mxp[p], c[mi][ni][e]);
                }
        __syncthreads();
    }

    // ---- cross-t4 max, per-warp partials -> stats (qb alias: Q MMAs done)
    #pragma unroll
    for (int o = 1; o <= 2; o <<= 1) {
        #pragma unroll
        for (int p = 0; p < 4; p++)
            mxp[p] = fmaxf(mxp[p], __shfl_xor_sync(0xffffffffu, mxp[p], o));
    }
    if (t4 == 0) {
        qb[(g)      * 8 + w] = __float_as_uint(mxp[0]);
        qb[(g + 8)  * 8 + w] = __float_as_uint(mxp[1]);
        qb[(g + 16) * 8 + w] = __float_as_uint(mxp[2]);
        qb[(g + 24) * 8 + w] = __float_as_uint(mxp[3]);
    }
    __syncthreads();

    // ---- row max; exp+sum (thread: row tid>>3, cols (tid&7)*4 + 32j)
    {
        const int srow = tid >> 3, l8 = tid & 7;
        float mx = -1e30f;
        #pragma unroll
        for (int i = 0; i < 8; i++)
            mx = fmaxf(mx, __uint_as_float(qb[srow * 8 + i]));

        float sum = 0.f;
        #pragma unroll
        for (int j = 0; j < 32; j++) {
            uint32_t* p = &sc[srow * SC_STR + l8 * 4 + 32 * j];
            uint4 u = *(uint4*)p;
            float x0 = __expf(__uint_as_float(u.x) - mx);
            float x1 = __expf(__uint_as_float(u.y) - mx);
            float x2 = __expf(__uint_as_float(u.z) - mx);
            float x3 = __expf(__uint_as_float(u.w) - mx);
            sum += (x0 + x1) + (x2 + x3);
            u.x = __float_as_uint(x0); u.y = __float_as_uint(x1);
            u.z = __float_as_uint(x2); u.w = __float_as_uint(x3);
            *(uint4*)p = u;
        }
        #pragma unroll
        for (int o = 1; o <= 4; o <<= 1)
            sum += __shfl_xor_sync(0xffffffffu, sum, o);
        if (l8 == 0) qb[512 + srow] = __float_as_uint(1.f / sum);
    }
    __syncthreads();

    // ---- masked normalize: f32 -> g_sc (for avg), tf32 -> sc (for PV)
    {
        float* out = g_sc + (size_t)z * (1024 * 1024) + (size_t)t0 * 1024;
        #pragma unroll
        for (int r = 0; r < 32; r++) {
            int idx = tid + r * 256;             // 8192 f4
            int rr = idx >> 8, c4 = (idx & 255) * 4;
            uint4 u = *(uint4*)&sc[rr * SC_STR + c4];
            float inv = __uint_as_float(qb[512 + rr]);
            float4 mk = *(const float4*)(mask + ((size_t)(b * 1024 + t0 + rr)) * 1024 + c4);
            float4 o4;
            o4.x = __uint_as_float(u.x) * inv * mk.x;
            o4.y = __uint_as_float(u.y) * inv * mk.y;
            o4.z = __uint_as_float(u.z) * inv * mk.z;
            o4.w = __uint_as_float(u.w) * inv * mk.w;
            *(float4*)(out + (size_t)rr * 1024 + c4) = o4;
            uint4 t;
            t.x = f2tf32(o4.x); t.y = f2tf32(o4.y);
            t.z = f2tf32(o4.z); t.w = f2tf32(o4.w);
            *(uint4*)&sc[rr * SC_STR + c4] = t;
        }
    }
    __syncthreads();

    // ---- PV: ctx[32][64] = P(sc, tf32) x Vt chunks; warp tile 16x16
    const int miw = w & 1;
    const int n0v = (w >> 1) * 16;
    float cc[2][4];
    #pragma unroll
    for (int ni = 0; ni < 2; ni++)
        #pragma unroll
        for (int e = 0; e < 4; e++) cc[ni][e] = 0.f;

    auto loadV = [&](uint32_t* dst, int s0) {
        #pragma unroll
        for (int r = 0; r < 8; r++) {
            int idx = tid + r * 256;          // 2048 f4 = 64 d-rows x 128 s
            int d = idx >> 5, c4 = (idx & 31) * 4;
            float4 v = *(const float4*)(g_vt + (size_t)(z * 64 + d) * 1024 + s0 + c4);
            uint4 u = {f2tf32(v.x), f2tf32(v.y), f2tf32(v.z), f2tf32(v.w)};
            *(uint4*)&dst[d * 132 + c4] = u;
        }
    };
    loadV(kv0, 0);
    __syncthreads();

    for (int ch = 0; ch < 8; ch++) {
        uint32_t* vb = (ch & 1) ? kv1 : kv0;
        if (ch < 7) loadV((ch & 1) ? kv0 : kv1, (ch + 1) * 128);

        int s0 = ch * 128;
        #pragma unroll
        for (int kk = 0; kk < 16; kk++) {
            int col = kk * 8 + t4;
            uint32_t a[4], bb[2][2];
            int r = miw * 16 + g;
            a[0] = sc[r * SC_STR + s0 + col];
            a[1] = sc[(r + 8) * SC_STR + s0 + col];
            a[2] = sc[r * SC_STR + s0 + col + 4];
            a[3] = sc[(r + 8) * SC_STR + s0 + col + 4];
            #pragma unroll
            for (int ni = 0; ni < 2; ni++) {
                bb[ni][0] = vb[(n0v + ni * 8 + g) * 132 + col];
                bb[ni][1] = vb[(n0v + ni * 8 + g) * 132 + col + 4];
            }
            #pragma unroll
            for (int ni = 0; ni < 2; ni++)
                mma16n8k8(cc[ni], a, bb[ni]);
        }
        __syncthreads();
    }

    // ---- ctx staging (qb, stride 68) + coalesced store to [t,b,e]
    #pragma unroll
    for (int ni = 0; ni < 2; ni++)
        #pragma unroll
        for (int e = 0; e < 4; e++) {
            int row = miw * 16 + g + ((e >= 2) ? 8 : 0);
            int col = n0v + ni * 8 + t4 * 2 + (e & 1);
            qb[row * 68 + col] = __float_as_uint(cc[ni][e]);
        }
    __syncthreads();
    #pragma unroll
    for (int r = 0; r < 2; r++) {
        int idx = tid + r * 256;
        int row = idx >> 4, c4 = (idx & 15) * 4;
        uint4 u = *(uint4*)&qb[row * 68 + c4];
        *(uint4*)&g_ctx2[(size_t)((t0 + row) * 4 + b) * 1024 + fq + c4] = u;
    }
}

// ============================================================================
// avg[b][t][s] = (1/16) * sum_h g_sc[b*16+h][t][s]   (streaming, f4)
// ============================================================================
__global__ __launch_bounds__(256)
void avg_sum(float* __restrict__ avg_out)
{
    size_t i = (size_t)blockIdx.x * 256 + threadIdx.x;   // 1M f4 outputs
    int b = (int)(i >> 18);
    size_t r = i & 262143;
    const float4* base = (const float4*)g_sc + (size_t)(b * 16) * 262144 + r;
    float4 s = {0.f, 0.f, 0.f, 0.f};
    #pragma unroll
    for (int h = 0; h < 16; h++) {
        float4 v = base[(size_t)h * 262144];
        s.x += v.x; s.y += v.y; s.z += v.z; s.w += v.w;
    }
    float4 o = {s.x * 0.0625f, s.y * 0.0625f, s.z * 0.0625f, s.w * 0.0625f};
    ((float4*)avg_out)[i] = o;
}

// ---------------------------------------------------------------------------
extern "C" void kernel_launch(void* const* d_in, const int* in_sizes, int n_in,
                              void* d_out, int out_size)
{
    const float* query = (const float*)d_in[0];
    const float* key   = (const float*)d_in[1];
    const float* mask  = (const float*)d_in[2];
    const float* w_in  = (const float*)d_in[3];
    const float* b_in  = (const float*)d_in[4];
    const float* w_out = (const float*)d_in[5];
    const float* b_out = (const float*)d_in[6];
    float* out = (float*)d_out;                         // [t][b][e]
    float* avg = out + (size_t)T_LEN * BSZ * EMB;       // [b][t][s]

    cudaFuncSetAttribute(attn_fused, cudaFuncAttributeMaxDynamicSharedMemorySize,
                         ATT_SMEM_BYTES);

    // 1) Q projection  -> g_q (scaled), 512 CTAs
    gemm_mma<0><<<dim3(16, 32), 256>>>(query, w_in, b_in, nullptr);
    // 2) KV projection -> g_k row-major, g_vt transposed, 1024 CTAs
    gemm_mma<1><<<dim3(32, 32), 256>>>(key, w_in + EMB * EMB, b_in + EMB, nullptr);
    // 3) fused scores+softmax+mask+PV -> g_sc (probs), g_ctx2
    attn_fused<<<dim3(32, 64), 256, ATT_SMEM_BYTES>>>(mask);
    // 4) avg over heads -> avg output
    avg_sum<<<4096, 256>>>(avg);
    // 5) output projection -> d_out
    gemm_mma<3><<<dim3(16, 32), 256>>>(nullptr, w_out, b_out, out);
}

// round 11
// speedup vs baseline: 1.2393x; 1.0688x over previous
#include <cuda_runtime.h>
#include <cstdint>

#define T_LEN 1024
#define S_LEN 1024
#define BSZ 4
#define EMB 1024
#define NH 16
#define HD 64

// ---------------- scratch (device globals) ----------------------------------
__device__ float g_q[4096 * 1024];                   // [m=t*4+b][f=h*64+d], scaled
__device__ float g_k[4096 * 1024];                   // [m=s*4+b][f=h*64+d]
__device__ float g_vt[64 * 64 * 1024];               // [z=(b,h)][d][s]  (V transposed)
__device__ float g_sc[(size_t)64 * 1024 * 1024];     // scores -> masked probs [z][t][s]
__device__ float g_ctx2[4096 * 1024];                // [m=t*4+b][e]

// ============================================================================
__device__ __forceinline__ uint32_t f2tf32(float f) {
    uint32_t u;
    asm("cvt.rna.tf32.f32 %0, %1;" : "=r"(u) : "f"(f));
    return u;
}
__device__ __forceinline__ void mma16n8k8(float* c, const uint32_t* a, const uint32_t* b) {
    asm volatile(
        "mma.sync.aligned.m16n8k8.row.col.f32.tf32.tf32.f32 "
        "{%0,%1,%2,%3}, {%4,%5,%6,%7}, {%8,%9}, {%0,%1,%2,%3};"
        : "+f"(c[0]), "+f"(c[1]), "+f"(c[2]), "+f"(c[3])
        : "r"(a[0]), "r"(a[1]), "r"(a[2]), "r"(a[3]), "r"(b[0]), "r"(b[1]));
}

#define SROW 20

// ============================================================================
// Projection GEMM (tf32 mma.sync NT), tile 128x64, 8 warps (4m x 2n),
// warp tile 32x32. Double-buffered BK=16.
//  MODE 0: g_q[m][col]  = (v+bias)*0.125          grid (16,32)
//  MODE 1: col<1024 -> g_k[m][col]=v+bias; else V scatter to g_vt  grid (32,32)
//  MODE 3: Cout[m][col] = v+bias                  grid (16,32)
// ============================================================================
template<int MODE>
__global__ __launch_bounds__(256)
void gemm_mma(const float* __restrict__ Ain,
              const float* __restrict__ Bin,
              const float* __restrict__ bias,
              float* __restrict__ Cout)
{
    __shared__ uint32_t As[2][128 * SROW];
    __shared__ uint32_t Bs[2][64 * SROW];

    const int tid = threadIdx.x;
    const int wid = tid >> 5, lane = tid & 31;
    const int wm = wid & 3, wn = wid >> 2;
    const int g = lane >> 2, t4 = lane & 3;
    const int m0 = blockIdx.y * 128;
    const int n0 = blockIdx.x * 64;

    const float* A = (MODE == 3) ? g_ctx2 : Ain;
    const float* B = Bin;

    auto load_stage = [&](int s, int k0) {
        #pragma unroll
        for (int r = 0; r < 2; r++) {
            int f4 = tid + r * 256;
            int row = f4 >> 2, c4 = (f4 & 3) * 4;
            float4 v = *(const float4*)(A + (size_t)(m0 + row) * 1024 + k0 + c4);
            uint4 u = {f2tf32(v.x), f2tf32(v.y), f2tf32(v.z), f2tf32(v.w)};
            *(uint4*)&As[s][row * SROW + c4] = u;
        }
        {
            int row = tid >> 2, c4 = (tid & 3) * 4;
            float4 v = *(const float4*)(B + (size_t)(n0 + row) * 1024 + k0 + c4);
            uint4 u = {f2tf32(v.x), f2tf32(v.y), f2tf32(v.z), f2tf32(v.w)};
            *(uint4*)&Bs[s][row * SROW + c4] = u;
        }
    };

    float c[2][4][4];
    #pragma unroll
    for (int mi = 0; mi < 2; mi++)
        #pragma unroll
        for (int ni = 0; ni < 4; ni++)
            #pragma unroll
            for (int e = 0; e < 4; e++) c[mi][ni][e] = 0.f;

    load_stage(0, 0);
    __syncthreads();

    for (int i = 0; i < 64; i++) {
        int s = i & 1;
        #pragma unroll
        for (int kk = 0; kk < 2; kk++) {
            uint32_t a[2][4], b[4][2];
            int col = kk * 8 + t4;
            #pragma unroll
            for (int mi = 0; mi < 2; mi++) {
                int r = wm * 32 + mi * 16 + g;
                a[mi][0] = As[s][r * SROW + col];
                a[mi][1] = As[s][(r + 8) * SROW + col];
                a[mi][2] = As[s][r * SROW + col + 4];
                a[mi][3] = As[s][(r + 8) * SROW + col + 4];
            }
            #pragma unroll
            for (int ni = 0; ni < 4; ni++) {
                int rn = wn * 32 + ni * 8 + g;
                b[ni][0] = Bs[s][rn * SROW + col];
                b[ni][1] = Bs[s][rn * SROW + col + 4];
            }
            #pragma unroll
            for (int mi = 0; mi < 2; mi++)
                #pragma unroll
                for (int ni = 0; ni < 4; ni++)
                    mma16n8k8(c[mi][ni], a[mi], b[ni]);
        }
        if (i + 1 < 64) {
            load_stage(s ^ 1, (i + 1) * 16);
            __syncthreads();
        }
    }

    #pragma unroll
    for (int mi = 0; mi < 2; mi++) {
        #pragma unroll
        for (int ni = 0; ni < 4; ni++) {
            #pragma unroll
            for (int e = 0; e < 4; e++) {
                int row = m0 + wm * 32 + mi * 16 + g + ((e >= 2) ? 8 : 0);
                int col = n0 + wn * 32 + ni * 8 + t4 * 2 + (e & 1);
                float v = c[mi][ni][e] + bias[col];
                if (MODE == 0) {
                    g_q[(size_t)row * 1024 + col] = v * 0.125f;
                } else if (MODE == 1) {
                    if (col < 1024) {
                        g_k[(size_t)row * 1024 + col] = v;
                    } else {
                        int ff = col - 1024;
                        int h = ff >> 6, d = ff & 63;
                        int s = row >> 2, b = row & 3;
                        g_vt[(size_t)(((b << 4) + h) * 64 + d) * 1024 + s] = v;
                    }
                } else {
                    Cout[(size_t)row * 1024 + col] = v;
                }
            }
        }
    }
}

// ============================================================================
// Scores GEMM: per (s-blk, t-blk, z): 128x128 tile, K=64.
// A row = t from g_q[(t*4+b)*1024+fq+k]; B row = s from g_k[(s*4+b)*1024+fq+k].
// 8 warps (4m x 2n), warp tile 32x64. Raw scores -> g_sc.
// ============================================================================
__global__ __launch_bounds__(256)
void scores_gemm()
{
    __shared__ uint32_t As[2][128 * SROW];
    __shared__ uint32_t Bs[2][128 * SROW];

    const int tid = threadIdx.x;
    const int wid = tid >> 5, lane = tid & 31;
    const int wm = wid & 3, wn = wid >> 2;
    const int g = lane >> 2, t4 = lane & 3;
    const int s0b = blockIdx.x * 128;
    const int t0 = blockIdx.y * 128;
    const int z  = blockIdx.z;
    const int b  = z >> 4;
    const int fq = (z & 15) * HD;

    auto load_stage = [&](int s, int k0) {
        #pragma unroll
        for (int r = 0; r < 2; r++) {
            int f4 = tid + r * 256;
            int row = f4 >> 2, c4 = (f4 & 3) * 4;
            float4 v = *(const float4*)(g_q + (size_t)((t0 + row) * 4 + b) * 1024 + fq + k0 + c4);
            uint4 u = {f2tf32(v.x), f2tf32(v.y), f2tf32(v.z), f2tf32(v.w)};
            *(uint4*)&As[s][row * SROW + c4] = u;
        }
        #pragma unroll
        for (int r = 0; r < 2; r++) {
            int f4 = tid + r * 256;
            int row = f4 >> 2, c4 = (f4 & 3) * 4;
            float4 v = *(const float4*)(g_k + (size_t)((s0b + row) * 4 + b) * 1024 + fq + k0 + c4);
            uint4 u = {f2tf32(v.x), f2tf32(v.y), f2tf32(v.z), f2tf32(v.w)};
            *(uint4*)&Bs[s][row * SROW + c4] = u;
        }
    };

    float c[2][8][4];
    #pragma unroll
    for (int mi = 0; mi < 2; mi++)
        #pragma unroll
        for (int ni = 0; ni < 8; ni++)
            #pragma unroll
            for (int e = 0; e < 4; e++) c[mi][ni][e] = 0.f;

    load_stage(0, 0);
    __syncthreads();

    #pragma unroll
    for (int i = 0; i < 4; i++) {
        int s = i & 1;
        #pragma unroll
        for (int kk = 0; kk < 2; kk++) {
            uint32_t a[2][4], b[8][2];
            int col = kk * 8 + t4;
            #pragma unroll
            for (int mi = 0; mi < 2; mi++) {
                int r = wm * 32 + mi * 16 + g;
                a[mi][0] = As[s][r * SROW + col];
                a[mi][1] = As[s][(r + 8) * SROW + col];
                a[mi][2] = As[s][r * SROW + col + 4];
                a[mi][3] = As[s][(r + 8) * SROW + col + 4];
            }
            #pragma unroll
            for (int ni = 0; ni < 8; ni++) {
                int rn = wn * 64 + ni * 8 + g;
                b[ni][0] = Bs[s][rn * SROW + col];
                b[ni][1] = Bs[s][rn * SROW + col + 4];
            }
            #pragma unroll
            for (int mi = 0; mi < 2; mi++)
                #pragma unroll
                for (int ni = 0; ni < 8; ni++)
                    mma16n8k8(c[mi][ni], a[mi], b[ni]);
        }
        if (i + 1 < 4) {
            load_stage(s ^ 1, (i + 1) * 16);
            __syncthreads();
        }
    }

    float* out = g_sc + (size_t)z * (1024 * 1024);
    #pragma unroll
    for (int mi = 0; mi < 2; mi++) {
        #pragma unroll
        for (int ni = 0; ni < 8; ni++) {
            #pragma unroll
            for (int e = 0; e < 4; e++) {
                int row = t0 + wm * 32 + mi * 16 + g + ((e >= 2) ? 8 : 0);
                int col = s0b + wn * 64 + ni * 8 + t4 * 2 + (e & 1);
                out[(size_t)row * 1024 + col] = c[mi][ni][e];
            }
        }
    }
}

// ============================================================================
// Softmax + mask, one warp per (z,t) row; full row (1024 f) in 32 regs.
// In-place on g_sc: raw scores -> masked normalized probs.
// ============================================================================
__global__ __launch_bounds__(256)
void softmax_warp(const float* __restrict__ mask)
{
    const int row = blockIdx.x * 8 + (threadIdx.x >> 5);   // z*1024 + t
    const int lane = threadIdx.x & 31;
    const int z = row >> 10, t = row & 1023;
    const int b = z >> 4;

    float4* rp = (float4*)(g_sc + (size_t)row * 1024) + lane;
    float4 x[8];
    #pragma unroll
    for (int i = 0; i < 8; i++) x[i] = rp[i * 32];

    float mx = -1e30f;
    #pragma unroll
    for (int i = 0; i < 8; i++) {
        mx = fmaxf(mx, fmaxf(fmaxf(x[i].x, x[i].y), fmaxf(x[i].z, x[i].w)));
    }
    #pragma unroll
    for (int o = 16; o >= 1; o >>= 1)
        mx = fmaxf(mx, __shfl_xor_sync(0xffffffffu, mx, o));

    float sum = 0.f;
    #pragma unroll
    for (int i = 0; i < 8; i++) {
        x[i].x = __expf(x[i].x - mx);
        x[i].y = __expf(x[i].y - mx);
        x[i].z = __expf(x[i].z - mx);
        x[i].w = __expf(x[i].w - mx);
        sum += (x[i].x + x[i].y) + (x[i].z + x[i].w);
    }
    #pragma unroll
    for (int o = 16; o >= 1; o >>= 1)
        sum += __shfl_xor_sync(0xffffffffu, sum, o);
    const float inv = 1.f / sum;

    const float4* mrow = (const float4*)(mask + ((size_t)(b * 1024 + t)) * 1024) + lane;
    #pragma unroll
    for (int i = 0; i < 8; i++) {
        float4 mk = mrow[i * 32];
        float4 o4;
        o4.x = x[i].x * inv * mk.x;
        o4.y = x[i].y * inv * mk.y;
        o4.z = x[i].z * inv * mk.z;
        o4.w = x[i].w * inv * mk.w;
        rp[i * 32] = o4;
    }
}

// ============================================================================
// PV GEMM: per (t-blk, z): C[128 t][64 d] = P[128,1024] x Vt[64,1024]^T (NT).
// 8 warps (4m x 2n), warp tile 32x32, K=1024 double-buffered.
// ctx scattered directly to [t,b,e] rows of g_ctx2 (coalesced f1 per thread).
// ============================================================================
__global__ __launch_bounds__(256)
void pv_gemm()
{
    __shared__ uint32_t As[2][128 * SROW];
    __shared__ uint32_t Bs[2][64 * SROW];

    const int tid = threadIdx.x;
    const int wid = tid >> 5, lane = tid & 31;
    const int wm = wid & 3, wn = wid >> 2;
    const int g = lane >> 2, t4 = lane & 3;
    const int t0 = blockIdx.x * 128;
    const int z  = blockIdx.y;
    const int b  = z >> 4;
    const int fq = (z & 15) * HD;

    const float* A = g_sc + (size_t)z * (1024 * 1024);
    const float* B = g_vt + (size_t)z * (64 * 1024);

    auto load_stage = [&](int s, int k0) {
        #pragma unroll
        for (int r = 0; r < 2; r++) {
            int f4 = tid + r * 256;
            int row = f4 >> 2, c4 = (f4 & 3) * 4;
            float4 v = *(const float4*)(A + (size_t)(t0 + row) * 1024 + k0 + c4);
            uint4 u = {f2tf32(v.x), f2tf32(v.y), f2tf32(v.z), f2tf32(v.w)};
            *(uint4*)&As[s][row * SROW + c4] = u;
        }
        {
            int row = tid >> 2, c4 = (tid & 3) * 4;
            float4 v = *(const float4*)(B + (size_t)row * 1024 + k0 + c4);
            uint4 u = {f2tf32(v.x), f2tf32(v.y), f2tf32(v.z), f2tf32(v.w)};
            *(uint4*)&Bs[s][row * SROW + c4] = u;
        }
    };

    float c[2][4][4];
    #pragma unroll
    for (int mi = 0; mi < 2; mi++)
        #pragma unroll
        for (int ni = 0; ni < 4; ni++)
            #pragma unroll
            for (int e = 0; e < 4; e++) c[mi][ni][e] = 0.f;

    load_stage(0, 0);
    __syncthreads();

    for (int i = 0; i < 64; i++) {
        int s = i & 1;
        #pragma unroll
        for (int kk = 0; kk < 2; kk++) {
            uint32_t a[2][4], bb[4][2];
            int col = kk * 8 + t4;
            #pragma unroll
            for (int mi = 0; mi < 2; mi++) {
                int r = wm * 32 + mi * 16 + g;
                a[mi][0] = As[s][r * SROW + col];
                a[mi][1] = As[s][(r + 8) * SROW + col];
                a[mi][2] = As[s][r * SROW + col + 4];
                a[mi][3] = As[s][(r + 8) * SROW + col + 4];
            }
            #pragma unroll
            for (int ni = 0; ni < 4; ni++) {
                int rn = wn * 32 + ni * 8 + g;
                bb[ni][0] = Bs[s][rn * SROW + col];
                bb[ni][1] = Bs[s][rn * SROW + col + 4];
            }
            #pragma unroll
            for (int mi = 0; mi < 2; mi++)
                #pragma unroll
                for (int ni = 0; ni < 4; ni++)
                    mma16n8k8(c[mi][ni], a[mi], bb[ni]);
        }
        if (i + 1 < 64) {
            load_stage(s ^ 1, (i + 1) * 16);
            __syncthreads();
        }
    }

    #pragma unroll
    for (int mi = 0; mi < 2; mi++) {
        #pragma unroll
        for (int ni = 0; ni < 4; ni++) {
            #pragma unroll
            for (int e = 0; e < 4; e++) {
                int row = t0 + wm * 32 + mi * 16 + g + ((e >= 2) ? 8 : 0);
                int col = wn * 32 + ni * 8 + t4 * 2 + (e & 1);
                g_ctx2[(size_t)(row * 4 + b) * 1024 + fq + col] = c[mi][ni][e];
            }
        }
    }
}

// ============================================================================
// avg[b][t][s] = (1/16) * sum_h g_sc[b*16+h][t][s]   (streaming, f4)
// ============================================================================
__global__ __launch_bounds__(256)
void avg_sum(float* __restrict__ avg_out)
{
    size_t i = (size_t)blockIdx.x * 256 + threadIdx.x;   // 1M f4 outputs
    int b = (int)(i >> 18);
    size_t r = i & 262143;
    const float4* base = (const float4*)g_sc + (size_t)(b * 16) * 262144 + r;
    float4 s = {0.f, 0.f, 0.f, 0.f};
    #pragma unroll
    for (int h = 0; h < 16; h++) {
        float4 v = base[(size_t)h * 262144];
        s.x += v.x; s.y += v.y; s.z += v.z; s.w += v.w;
    }
    float4 o = {s.x * 0.0625f, s.y * 0.0625f, s.z * 0.0625f, s.w * 0.0625f};
    ((float4*)avg_out)[i] = o;
}

// ---------------------------------------------------------------------------
extern "C" void kernel_launch(void* const* d_in, const int* in_sizes, int n_in,
                              void* d_out, int out_size)
{
    const float* query = (const float*)d_in[0];
    const float* key   = (const float*)d_in[1];
    const float* mask  = (const float*)d_in[2];
    const float* w_in  = (const float*)d_in[3];
    const float* b_in  = (const float*)d_in[4];
    const float* w_out = (const float*)d_in[5];
    const float* b_out = (const float*)d_in[6];
    float* out = (float*)d_out;                         // [t][b][e]
    float* avg = out + (size_t)T_LEN * BSZ * EMB;       // [b][t][s]

    // 1) Q projection  -> g_q (scaled)
    gemm_mma<0><<<dim3(16, 32), 256>>>(query, w_in, b_in, nullptr);
    // 2) KV projection -> g_k row-major, g_vt transposed
    gemm_mma<1><<<dim3(32, 32), 256>>>(key, w_in + EMB * EMB, b_in + EMB, nullptr);
    // 3) scores (raw) -> g_sc
    scores_gemm<<<dim3(8, 8, 64), 256>>>();
    // 4) softmax + mask in place on g_sc (warp per row)
    softmax_warp<<<8192, 256>>>(mask);
    // 5) PV -> g_ctx2 ([t,b,e])
    pv_gemm<<<dim3(8, 64), 256>>>();
    // 6) avg over heads -> avg output
    avg_sum<<<4096, 256>>>(avg);
    // 7) output projection -> d_out
    gemm_mma<3><<<dim3(16, 32), 256>>>(nullptr, w_out, b_out, out);
}

// round 12
// speedup vs baseline: 2.1080x; 1.7009x over previous
#include <cuda_runtime.h>
#include <cuda_fp16.h>
#include <cstdint>

#define T_LEN 1024
#define S_LEN 1024
#define BSZ 4
#define EMB 1024
#define NH 16
#define HD 64

// ---------------- scratch (device globals) ----------------------------------
__device__ __half g_q[4096 * 1024];                  // [m=t*4+b][f=h*64+d], scaled
__device__ __half g_k[4096 * 1024];                  // [m=s*4+b][f]
__device__ __half g_vth[64 * 64 * 1024];             // [z=(b,h)][d][s] (V transposed)
__device__ float  g_sc[(size_t)64 * 1024 * 1024];    // raw scores [z][t][s] (f32)
__device__ __half g_sch[(size_t)64 * 1024 * 1024];   // masked probs [z][t][s] (fp16)
__device__ __half g_ctx2[4096 * 1024];               // [m=t*4+b][e] (fp16)

// ============================================================================
__device__ __forceinline__ void mma16n8k16(float* c, const uint32_t* a, const uint32_t* b) {
    asm volatile(
        "mma.sync.aligned.m16n8k16.row.col.f32.f16.f16.f32 "
        "{%0,%1,%2,%3}, {%4,%5,%6,%7}, {%8,%9}, {%0,%1,%2,%3};"
        : "+f"(c[0]), "+f"(c[1]), "+f"(c[2]), "+f"(c[3])
        : "r"(a[0]), "r"(a[1]), "r"(a[2]), "r"(a[3]), "r"(b[0]), "r"(b[1]));
}

// ============================================================================
// fp16 NT GEMM, tile 128x64, 8 warps (4m x 2n), warp tile 32x32, BK=32 halfs,
// double buffered. Stride 40 halfs (conflict-free frags).
//  MODE 0: Qproj  A=query f32, B=Wq f32   -> g_q fp16 ((v+b)*0.125)
//  MODE 1: KVproj A=key f32, B=Wkv f32    -> g_k fp16 / g_vth fp16 scatter
//  MODE 3: outproj A=g_ctx2 fp16, B=Wout f32 -> Cout f32 (+bias)
//  MODE 4: PV     A=g_sch[z] fp16, B=g_vth[z] fp16 -> g_ctx2 fp16
// ============================================================================
template<int MODE>
__global__ __launch_bounds__(256)
void gemm_h(const float* __restrict__ Af,
            const float* __restrict__ Bf,
            const float* __restrict__ bias,
            float* __restrict__ Cout)
{
    __shared__ __align__(16) __half As[2][128 * 40];
    __shared__ __align__(16) __half Bs[2][64 * 40];

    const int tid = threadIdx.x;
    const int wid = tid >> 5, lane = tid & 31;
    const int wm = wid & 3, wn = wid >> 2;
    const int g = lane >> 2, t4 = lane & 3;

    int m0, n0, z = 0, bq = 0, fq = 0;
    if constexpr (MODE == 4) {
        m0 = blockIdx.x * 128; n0 = 0; z = blockIdx.y;
        bq = z >> 4; fq = (z & 15) * 64;
    } else {
        m0 = blockIdx.y * 128; n0 = blockIdx.x * 64;
    }

    const __half* Ah = nullptr;
    const __half* Bh = nullptr;
    if constexpr (MODE == 3) Ah = g_ctx2;
    if constexpr (MODE == 4) {
        Ah = g_sch + (size_t)z * 1024 * 1024;
        Bh = g_vth + (size_t)z * 64 * 1024;
    }

    auto load_stage = [&](int s, int k0) {
        // ---- A tile 128 x 32
        if constexpr (MODE == 0 || MODE == 1) {
            #pragma unroll
            for (int r = 0; r < 4; r++) {
                int idx = tid + r * 256;
                int row = idx >> 3, c4 = (idx & 7) * 4;
                float4 v = *(const float4*)(Af + (size_t)(m0 + row) * 1024 + k0 + c4);
                __half2 p0 = __floats2half2_rn(v.x, v.y);
                __half2 p1 = __floats2half2_rn(v.z, v.w);
                uint2 u = make_uint2(*(const uint32_t*)&p0, *(const uint32_t*)&p1);
                *(uint2*)&As[s][row * 40 + c4] = u;
            }
        } else {
            #pragma unroll
            for (int r = 0; r < 2; r++) {
                int idx = tid + r * 256;
                int row = idx >> 2, c8 = (idx & 3) * 8;
                uint4 u = *(const uint4*)(Ah + (size_t)(m0 + row) * 1024 + k0 + c8);
                *(uint4*)&As[s][row * 40 + c8] = u;
            }
        }
        // ---- B tile 64 x 32
        if constexpr (MODE == 4) {
            int row = tid >> 2, c8 = (tid & 3) * 8;
            uint4 u = *(const uint4*)(Bh + (size_t)row * 1024 + k0 + c8);
            *(uint4*)&Bs[s][row * 40 + c8] = u;
        } else {
            #pragma unroll
            for (int r = 0; r < 2; r++) {
                int idx = tid + r * 256;
                int row = idx >> 3, c4 = (idx & 7) * 4;
                float4 v = *(const float4*)(Bf + (size_t)(n0 + row) * 1024 + k0 + c4);
                __half2 p0 = __floats2half2_rn(v.x, v.y);
                __half2 p1 = __floats2half2_rn(v.z, v.w);
                uint2 u = make_uint2(*(const uint32_t*)&p0, *(const uint32_t*)&p1);
                *(uint2*)&Bs[s][row * 40 + c4] = u;
            }
        }
    };

    float c[2][4][4];
    #pragma unroll
    for (int mi = 0; mi < 2; mi++)
        #pragma unroll
        for (int ni = 0; ni < 4; ni++)
            #pragma unroll
            for (int e = 0; e < 4; e++) c[mi][ni][e] = 0.f;

    load_stage(0, 0);
    __syncthreads();

    for (int i = 0; i < 32; i++) {
        int s = i & 1;
        #pragma unroll
        for (int ks = 0; ks < 2; ks++) {
            const int kb = ks * 16 + t4 * 2;
            uint32_t a[2][4], bfr[4][2];
            #pragma unroll
            for (int mi = 0; mi < 2; mi++) {
                int r = (wm * 32 + mi * 16 + g) * 40;
                a[mi][0] = *(const uint32_t*)&As[s][r + kb];
                a[mi][1] = *(const uint32_t*)&As[s][r + 320 + kb];
                a[mi][2] = *(const uint32_t*)&As[s][r + kb + 8];
                a[mi][3] = *(const uint32_t*)&As[s][r + 320 + kb + 8];
            }
            #pragma unroll
            for (int ni = 0; ni < 4; ni++) {
                int rn = (wn * 32 + ni * 8 + g) * 40;
                bfr[ni][0] = *(const uint32_t*)&Bs[s][rn + kb];
                bfr[ni][1] = *(const uint32_t*)&Bs[s][rn + kb + 8];
            }
            #pragma unroll
            for (int mi = 0; mi < 2; mi++)
                #pragma unroll
                for (int ni = 0; ni < 4; ni++)
                    mma16n8k16(c[mi][ni], a[mi], bfr[ni]);
        }
        if (i + 1 < 32) {
            load_stage(s ^ 1, (i + 1) * 32);
            __syncthreads();
        }
    }

    // ---- epilogue (pairs e0/e1 -> row, e2/e3 -> row+8; cols col0, col0+1)
    #pragma unroll
    for (int mi = 0; mi < 2; mi++) {
        #pragma unroll
        for (int ni = 0; ni < 4; ni++) {
            int r0 = m0 + wm * 32 + mi * 16 + g;
            int col0 = n0 + wn * 32 + ni * 8 + t4 * 2;
            #pragma unroll
            for (int half_i = 0; half_i < 2; half_i++) {
                int row = r0 + half_i * 8;
                float v0 = c[mi][ni][half_i * 2 + 0];
                float v1 = c[mi][ni][half_i * 2 + 1];
                if constexpr (MODE == 0) {
                    v0 = (v0 + bias[col0]) * 0.125f;
                    v1 = (v1 + bias[col0 + 1]) * 0.125f;
                    __half2 h = __floats2half2_rn(v0, v1);
                    *(__half2*)&g_q[(size_t)row * 1024 + col0] = h;
                } else if constexpr (MODE == 1) {
                    v0 += bias[col0]; v1 += bias[col0 + 1];
                    if (col0 < 1024) {
                        __half2 h = __floats2half2_rn(v0, v1);
                        *(__half2*)&g_k[(size_t)row * 1024 + col0] = h;
                    } else {
                        int ff = col0 - 1024;
                        int h_ = ff >> 6, d = ff & 63;
                        int sI = row >> 2, bI = row & 3;
                        size_t base = (size_t)(((bI << 4) + h_) * 64 + d) * 1024 + sI;
                        g_vth[base] = __float2half_rn(v0);
                        g_vth[base + 1024] = __float2half_rn(v1);
                    }
                } else if constexpr (MODE == 3) {
                    float2 o = {v0 + bias[col0], v1 + bias[col0 + 1]};
                    *(float2*)&Cout[(size_t)row * 1024 + col0] = o;
                } else {  // MODE 4: ctx -> [t,b,e] fp16
                    __half2 h = __floats2half2_rn(v0, v1);
                    *(__half2*)&g_ctx2[(size_t)(row * 4 + bq) * 1024 + fq + col0] = h;
                }
            }
        }
    }
}

// ============================================================================
// Scores GEMM fp16: per (s-blk, t-blk, z): 128x128 tile, K=64 (one load, no
// double buffer). 8 warps (4m x 2n), warp tile 32x64. Raw f32 scores -> g_sc.
// ============================================================================
__global__ __launch_bounds__(256)
void scores_gemm()
{
    __shared__ __align__(16) __half As[128 * 72];
    __shared__ __align__(16) __half Bs[128 * 72];

    const int tid = threadIdx.x;
    const int wid = tid >> 5, lane = tid & 31;
    const int wm = wid & 3, wn = wid >> 2;
    const int g = lane >> 2, t4 = lane & 3;
    const int s0b = blockIdx.x * 128;
    const int t0 = blockIdx.y * 128;
    const int z = blockIdx.z;
    const int b = z >> 4;
    const int fq = (z & 15) * 64;

    #pragma unroll
    for (int r = 0; r < 4; r++) {
        int idx = tid + r * 256;
        int row = idx >> 3, c8 = (idx & 7) * 8;
        uint4 ua = *(const uint4*)(g_q + (size_t)((t0 + row) * 4 + b) * 1024 + fq + c8);
        *(uint4*)&As[row * 72 + c8] = ua;
        uint4 ub = *(const uint4*)(g_k + (size_t)((s0b + row) * 4 + b) * 1024 + fq + c8);
        *(uint4*)&Bs[row * 72 + c8] = ub;
    }
    __syncthreads();

    float c[2][8][4];
    #pragma unroll
    for (int mi = 0; mi < 2; mi++)
        #pragma unroll
        for (int ni = 0; ni < 8; ni++)
            #pragma unroll
            for (int e = 0; e < 4; e++) c[mi][ni][e] = 0.f;

    #pragma unroll
    for (int step = 0; step < 4; step++) {
        const int kb = step * 16 + t4 * 2;
        uint32_t a[2][4], bfr[8][2];
        #pragma unroll
        for (int mi = 0; mi < 2; mi++) {
            int r = (wm * 32 + mi * 16 + g) * 72;
            a[mi][0] = *(const uint32_t*)&As[r + kb];
            a[mi][1] = *(const uint32_t*)&As[r + 576 + kb];
            a[mi][2] = *(const uint32_t*)&As[r + kb + 8];
            a[mi][3] = *(const uint32_t*)&As[r + 576 + kb + 8];
        }
        #pragma unroll
        for (int ni = 0; ni < 8; ni++) {
            int rn = (wn * 64 + ni * 8 + g) * 72;
            bfr[ni][0] = *(const uint32_t*)&Bs[rn + kb];
            bfr[ni][1] = *(const uint32_t*)&Bs[rn + kb + 8];
        }
        #pragma unroll
        for (int mi = 0; mi < 2; mi++)
            #pragma unroll
            for (int ni = 0; ni < 8; ni++)
                mma16n8k16(c[mi][ni], a[mi], bfr[ni]);
    }

    float* out = g_sc + (size_t)z * (1024 * 1024);
    #pragma unroll
    for (int mi = 0; mi < 2; mi++) {
        #pragma unroll
        for (int ni = 0; ni < 8; ni++) {
            int r0 = t0 + wm * 32 + mi * 16 + g;
            int col0 = s0b + wn * 64 + ni * 8 + t4 * 2;
            float2 o0 = {c[mi][ni][0], c[mi][ni][1]};
            float2 o1 = {c[mi][ni][2], c[mi][ni][3]};
            *(float2*)&out[(size_t)r0 * 1024 + col0] = o0;
            *(float2*)&out[(size_t)(r0 + 8) * 1024 + col0] = o1;
        }
    }
}

// ============================================================================
// Softmax + mask + avg, block per (b,t): 16 warps = 16 heads, row in regs.
// probs -> g_sch (fp16); block-reduce over smem staging -> avg output.
// ============================================================================
__global__ __launch_bounds__(512)
void softmax_avg(const float* __restrict__ mask, float* __restrict__ avg_out)
{
    __shared__ __half st[16][1024];

    const int bt = blockIdx.x;              // b*1024 + t
    const int b = bt >> 10, t = bt & 1023;
    const int tid = threadIdx.x;
    const int wid = tid >> 5, lane = tid & 31;
    const int z = b * 16 + wid;

    const float4* rp = (const float4*)(g_sc + ((size_t)z * 1024 + t) * 1024) + lane;
    float4 x[8];
    #pragma unroll
    for (int i = 0; i < 8; i++) x[i] = rp[i * 32];

    float mx = -1e30f;
    #pragma unroll
    for (int i = 0; i < 8; i++)
        mx = fmaxf(mx, fmaxf(fmaxf(x[i].x, x[i].y), fmaxf(x[i].z, x[i].w)));
    #pragma unroll
    for (int o = 16; o >= 1; o >>= 1)
        mx = fmaxf(mx, __shfl_xor_sync(0xffffffffu, mx, o));

    float sum = 0.f;
    #pragma unroll
    for (int i = 0; i < 8; i++) {
        x[i].x = __expf(x[i].x - mx);
        x[i].y = __expf(x[i].y - mx);
        x[i].z = __expf(x[i].z - mx);
        x[i].w = __expf(x[i].w - mx);
        sum += (x[i].x + x[i].y) + (x[i].z + x[i].w);
    }
    #pragma unroll
    for (int o = 16; o >= 1; o >>= 1)
        sum += __shfl_xor_sync(0xffffffffu, sum, o);
    const float inv = 1.f / sum;

    const float4* mrow = (const float4*)(mask + (size_t)bt * 1024) + lane;
    __half* prow = g_sch + ((size_t)z * 1024 + t) * 1024;
    #pragma unroll
    for (int i = 0; i < 8; i++) {
        float4 mk = mrow[i * 32];
        float p0 = x[i].x * inv * mk.x;
        float p1 = x[i].y * inv * mk.y;
        float p2 = x[i].z * inv * mk.z;
        float p3 = x[i].w * inv * mk.w;
        __half2 q0 = __floats2half2_rn(p0, p1);
        __half2 q1 = __floats2half2_rn(p2, p3);
        uint2 u = make_uint2(*(const uint32_t*)&q0, *(const uint32_t*)&q1);
        int coff = lane * 4 + 128 * i;
        *(uint2*)&prow[coff] = u;
        *(uint2*)&st[wid][coff] = u;
    }
    __syncthreads();

    float s0 = 0.f, s1 = 0.f;
    #pragma unroll
    for (int h = 0; h < 16; h++) {
        __half2 hv = *(const __half2*)&st[h][tid * 2];
        float2 f = __half22float2(hv);
        s0 += f.x; s1 += f.y;
    }
    float2 o = {s0 * 0.0625f, s1 * 0.0625f};
    *(float2*)&avg_out[(size_t)bt * 1024 + tid * 2] = o;
}

// ---------------------------------------------------------------------------
extern "C" void kernel_launch(void* const* d_in, const int* in_sizes, int n_in,
                              void* d_out, int out_size)
{
    const float* query = (const float*)d_in[0];
    const float* key   = (const float*)d_in[1];
    const float* mask  = (const float*)d_in[2];
    const float* w_in  = (const float*)d_in[3];
    const float* b_in  = (const float*)d_in[4];
    const float* w_out = (const float*)d_in[5];
    const float* b_out = (const float*)d_in[6];
    float* out = (float*)d_out;                         // [t][b][e]
    float* avg = out + (size_t)T_LEN * BSZ * EMB;       // [b][t][s]

    // 1) Q projection -> g_q fp16 (scaled)
    gemm_h<0><<<dim3(16, 32), 256>>>(query, w_in, b_in, nullptr);
    // 2) KV projection -> g_k fp16, g_vth fp16 (V transposed)
    gemm_h<1><<<dim3(32, 32), 256>>>(key, w_in + EMB * EMB, b_in + EMB, nullptr);
    // 3) scores (raw f32) -> g_sc
    scores_gemm<<<dim3(8, 8, 64), 256>>>();
    // 4) softmax + mask + avg -> g_sch (fp16 probs), avg output
    softmax_avg<<<4096, 512>>>(mask, avg);
    // 5) PV -> g_ctx2 fp16 ([t,b,e])
    gemm_h<4><<<dim3(8, 64), 256>>>(nullptr, nullptr, nullptr, nullptr);
    // 6) output projection -> d_out (f32)
    gemm_h<3><<<dim3(16, 32), 256>>>(nullptr, w_out, b_out, out);
}